// round 14
// baseline (speedup 1.0000x reference)
#include <cuda_runtime.h>
#include <cuda_fp16.h>
#include <cstdint>

// VACF via band-Gram, parallelogram tiling, mma.sync fp16 single-pass.
// K-chunks of 128 elems (12.8 chunks/CTA); f32 loaded by LDG directly into
// registers (two 8-slot waves, no smem staging) and converted to fp16 in-reg.
// 512 thr/CTA, 1 CTA/SM, 148 CTAs, chunk-balanced, last-CTA finalize.

#define T_DIM 10000
#define D_DIM 3000
#define D4    750
#define NTILE 79
#define NCHT  24                 // K chunks of 128 elems (24*128 = 3072)
#define UNITS (NTILE * NCHT)     // 1896
#define NCTA  148
#define NTHREADS 512
#define W_MAX 100
#define RB    240
#define STRB  272                // fp16 row stride bytes: 256 data + 16 pad
#define HTILE_B (RB * STRB)      // 65280
#define SMEM_B  (2 * HTILE_B)    // 130560
#define NSLOT (RB * 32)          // 7680 slots (16B f32 groups), 15/thread

__device__ double g_band[128];
__device__ unsigned g_done;

__device__ __forceinline__ void ldsm4(unsigned a, unsigned& r0, unsigned& r1,
                                      unsigned& r2, unsigned& r3) {
    asm volatile("ldmatrix.sync.aligned.m8n8.x4.shared.b16 {%0,%1,%2,%3}, [%4];"
                 : "=r"(r0), "=r"(r1), "=r"(r2), "=r"(r3) : "r"(a));
}

__device__ __forceinline__ void mma16816h(float* c, const unsigned* a, const unsigned* b) {
    asm("mma.sync.aligned.m16n8k16.row.col.f32.f16.f16.f32 "
        "{%0,%1,%2,%3}, {%4,%5,%6,%7}, {%8,%9}, {%0,%1,%2,%3};"
        : "+f"(c[0]), "+f"(c[1]), "+f"(c[2]), "+f"(c[3])
        : "r"(a[0]), "r"(a[1]), "r"(a[2]), "r"(a[3]), "r"(b[0]), "r"(b[1]));
}

__global__ __launch_bounds__(NTHREADS, 1) void vacf_gram(const float* __restrict__ vel,
                                                         float* __restrict__ out, int W) {
    extern __shared__ __align__(128) char sm[];
    __shared__ float s_band[W_MAX];
    __shared__ int s_last;

    const int tid  = threadIdx.x;
    const int warp = tid >> 5;
    const int lane = tid & 31;
    const int gB   = blockIdx.x;

    const unsigned smu = (unsigned)__cvta_generic_to_shared(sm);

    if (tid < W_MAX) s_band[tid] = 0.f;

    const int strip = warp >> 1;
    const int njpb  = (warp & 1) * 4;
    const int rl = lane & 7, gg = lane >> 3;
    const int arow  = 16 * strip + rl + ((gg & 1) << 3);
    const int acol0 = (gg >> 1) << 3;
    const int brow0 = 16 * strip + rl + ((gg >> 1) << 3);
    const int bcol0 = (gg & 1) << 3;

    int u  = (int)(((long)gB * UNITS) / NCTA);
    const int u1 = (int)(((long)(gB + 1) * UNITS) / NCTA);

    float c[8][4];
    float4 pf[8];

    while (u < u1) {
        const int tile = u / NCHT;
        const int cbeg = u % NCHT;
        const int cend = (cbeg + (u1 - u) < NCHT) ? cbeg + (u1 - u) : NCHT;
        const int R0   = tile * 128;
        u += cend - cbeg;

        #pragma unroll
        for (int i = 0; i < 8; i++)
            #pragma unroll
            for (int q = 0; q < 4; q++) c[i][q] = 0.f;

        // slot sid = tid + 512*(wv*8 + k): row = sid>>5, seg = sid&31
        // wave wv in {0,1}: k = 0..7 (wv=0), 0..6 (wv=1, sid<7680)

        auto ldg_wave = [&](int ci, int wv) {
            #pragma unroll
            for (int k = 0; k < 8; k++) {
                int sid = tid + ((wv * 8 + k) << 9);
                float4 v = make_float4(0.f, 0.f, 0.f, 0.f);
                if (sid < NSLOT) {
                    int row = sid >> 5;
                    int seg = sid & 31;
                    int gr  = R0 + row;
                    int c4  = ci * 32 + seg;
                    if (gr < T_DIM && c4 < D4)
                        v = *reinterpret_cast<const float4*>(
                            vel + (size_t)gr * D_DIM + c4 * 4);
                }
                pf[k] = v;
            }
        };

        auto cvt_wave = [&](int stw, int wv) {
            const unsigned hib = (unsigned)(stw * HTILE_B);
            #pragma unroll
            for (int k = 0; k < 8; k++) {
                int sid = tid + ((wv * 8 + k) << 9);
                if (sid < NSLOT) {
                    int row = sid >> 5;
                    int seg = sid & 31;
                    const float4 v = pf[k];
                    __half2 h01 = __float22half2_rn(make_float2(v.x, v.y));
                    __half2 h23 = __float22half2_rn(make_float2(v.z, v.w));
                    uint2 hh;
                    hh.x = *reinterpret_cast<unsigned*>(&h01);
                    hh.y = *reinterpret_cast<unsigned*>(&h23);
                    *reinterpret_cast<uint2*>(sm + hib + (row * STRB + seg * 8)) = hh;
                }
            }
        };

        auto kstep = [&](unsigned hib, int kk) {
            unsigned aoff = (unsigned)(arow * STRB + (kk + acol0) * 2);
            unsigned a[4];
            ldsm4(hib + aoff, a[0], a[1], a[2], a[3]);
            #pragma unroll
            for (int jl = 0; jl < 4; jl++) {
                const int njp = njpb + jl;
                unsigned boff = (unsigned)((brow0 + njp * 16) * STRB + (kk + bcol0) * 2);
                unsigned b[4];
                ldsm4(hib + boff, b[0], b[1], b[2], b[3]);
                const int lj = jl * 2;
                mma16816h(c[lj], a, &b[0]);
                if ((njp * 2 + 1) < 15) mma16816h(c[lj + 1], a, &b[2]);
            }
        };

        // ---- prologue: stage chunk cbeg into stage 0 ----
        ldg_wave(cbeg, 0);
        cvt_wave(0, 0);
        ldg_wave(cbeg, 1);
        cvt_wave(0, 1);
        __syncthreads();

        for (int ci = cbeg; ci < cend; ci++) {
            const int st  = (ci - cbeg) & 1;
            const unsigned hib = smu + (unsigned)(st * HTILE_B);
            const bool havenext = (ci + 1 < cend);

            if (havenext) ldg_wave(ci + 1, 0);   // latency covered by ksteps 0-3

            kstep(hib, 0);
            kstep(hib, 16);
            kstep(hib, 32);
            kstep(hib, 48);

            if (havenext) {
                cvt_wave(st ^ 1, 0);
                ldg_wave(ci + 1, 1);             // covered by ksteps 4-6
            }

            kstep(hib, 64);
            kstep(hib, 80);
            kstep(hib, 96);

            if (havenext) cvt_wave(st ^ 1, 1);

            kstep(hib, 112);

            // single barrier per chunk: publishes stage st^1, retires stage st
            __syncthreads();
        }

        // ---- segment epilogue: band extraction ----
        #pragma unroll
        for (int jl = 0; jl < 4; jl++)
            #pragma unroll
            for (int j = 0; j < 2; j++) {
                const int nj = (njpb + jl) * 2 + j;
                if (nj < 15)
                    #pragma unroll
                    for (int q = 0; q < 4; q++) {
                        int t = nj * 8 + ((lane & 3) << 1) + (q & 1)
                              - (lane >> 2) - ((q >> 1) << 3);
                        if (t >= 0 && t < W_MAX)
                            atomicAdd(&s_band[t], c[jl * 2 + j][q]);
                    }
            }
        __syncthreads();
        if (tid < W_MAX) {
            atomicAdd(&g_band[tid], (double)s_band[tid]);
            s_band[tid] = 0.f;
        }
        __syncthreads();
    }

    // ---- completion protocol: last CTA finalizes ----
    if (tid == 0) {
        __threadfence();
        unsigned p = atomicAdd(&g_done, 1u);
        s_last = (p == NCTA - 1);
    }
    __syncthreads();
    if (s_last) {
        __threadfence();
        if (tid < W_MAX && tid < W)
            out[tid] = (float)(g_band[tid] / ((double)(T_DIM - tid) * (double)D_DIM));
        if (tid < 128) g_band[tid] = 0.0;
        if (tid == 0) g_done = 0;
    }
}

extern "C" void kernel_launch(void* const* d_in, const int* in_sizes, int n_in,
                              void* d_out, int out_size) {
    const float* vel = (const float*)d_in[0];
    cudaFuncSetAttribute(vacf_gram, cudaFuncAttributeMaxDynamicSharedMemorySize, SMEM_B);
    vacf_gram<<<NCTA, NTHREADS, SMEM_B>>>(vel, (float*)d_out, out_size);
}